// round 2
// baseline (speedup 1.0000x reference)
#include <cuda_runtime.h>
#include <math.h>

#define B_TOK 16384
#define DIM   1024
#define HID   2048
#define NE    4
#define NC    3

#define BM 128
#define BN 128
#define BK 16
#define NSPLIT 4
#define NT_PER_SPLIT (HID / BN / NSPLIT)   // 4 N-tiles of 128 per split
#define KT (DIM / BK)                      // 64 k-tiles

// Scratch (device globals: allocation-free per harness rules)
__device__ float g_normed[(size_t)B_TOK * DIM];   // 64 MB
__device__ float g_gate[B_TOK * NE];

// ---------------- packed f32x2 helpers (FFMA2 path, full-rate fp32 on sm_103a) ----
__device__ __forceinline__ unsigned long long pk2(float lo, float hi) {
    unsigned long long r;
    asm("mov.b64 %0, {%1, %2};" : "=l"(r) : "f"(lo), "f"(hi));
    return r;
}
__device__ __forceinline__ void fma2(unsigned long long& d, unsigned long long a,
                                     unsigned long long b) {
    asm("fma.rn.f32x2 %0, %1, %2, %0;" : "+l"(d) : "l"(a), "l"(b));
}
__device__ __forceinline__ float2 upk2(unsigned long long v) {
    float2 r;
    asm("mov.b64 {%0, %1}, %2;" : "=f"(r.x), "=f"(r.y) : "l"(v));
    return r;
}
__device__ __forceinline__ float gelu_exact(float v) {
    return 0.5f * v * (1.0f + erff(v * 0.70710678118654752f));
}

// ========================= Kernel 1: LayerNorm + gate + out init ==================
__global__ __launch_bounds__(256) void ln_gate_kernel(
    const float* __restrict__ x,
    const float* __restrict__ gln_g, const float* __restrict__ gln_b,
    const float* __restrict__ gate_w, const float* __restrict__ gate_b,
    const float* __restrict__ ex_b2, float* __restrict__ out)
{
    const int row  = blockIdx.x;
    const int t    = threadIdx.x;
    const int lane = t & 31, warp = t >> 5;

    const float4 xv = *(const float4*)(x + (size_t)row * DIM + t * 4);
    float s  = xv.x + xv.y + xv.z + xv.w;
    float ss = xv.x * xv.x + xv.y * xv.y + xv.z * xv.z + xv.w * xv.w;
#pragma unroll
    for (int o = 16; o; o >>= 1) {
        s  += __shfl_xor_sync(0xffffffffu, s, o);
        ss += __shfl_xor_sync(0xffffffffu, ss, o);
    }
    __shared__ float rs[8], rss[8];
    if (lane == 0) { rs[warp] = s; rss[warp] = ss; }
    __syncthreads();
    s = 0.f; ss = 0.f;
#pragma unroll
    for (int w = 0; w < 8; w++) { s += rs[w]; ss += rss[w]; }
    const float mu   = s * (1.0f / DIM);
    const float var  = ss * (1.0f / DIM) - mu * mu;
    const float rstd = rsqrtf(var + 1e-5f);

    float4 nv;
    nv.x = (xv.x - mu) * rstd;
    nv.y = (xv.y - mu) * rstd;
    nv.z = (xv.z - mu) * rstd;
    nv.w = (xv.w - mu) * rstd;
    *(float4*)(g_normed + (size_t)row * DIM + t * 4) = nv;

    // gate logits: (normed*g+b) @ gate_w[D,4]
    const int d0 = t * 4;
    const float4 gg = *(const float4*)(gln_g + d0);
    const float4 gb = *(const float4*)(gln_b + d0);
    float y0 = fmaf(nv.x, gg.x, gb.x);
    float y1 = fmaf(nv.y, gg.y, gb.y);
    float y2 = fmaf(nv.z, gg.z, gb.z);
    float y3 = fmaf(nv.w, gg.w, gb.w);
    float l0 = 0.f, l1 = 0.f, l2 = 0.f, l3 = 0.f;
    float4 w;
    w = *(const float4*)(gate_w + (size_t)(d0 + 0) * NE);
    l0 += y0 * w.x; l1 += y0 * w.y; l2 += y0 * w.z; l3 += y0 * w.w;
    w = *(const float4*)(gate_w + (size_t)(d0 + 1) * NE);
    l0 += y1 * w.x; l1 += y1 * w.y; l2 += y1 * w.z; l3 += y1 * w.w;
    w = *(const float4*)(gate_w + (size_t)(d0 + 2) * NE);
    l0 += y2 * w.x; l1 += y2 * w.y; l2 += y2 * w.z; l3 += y2 * w.w;
    w = *(const float4*)(gate_w + (size_t)(d0 + 3) * NE);
    l0 += y3 * w.x; l1 += y3 * w.y; l2 += y3 * w.z; l3 += y3 * w.w;
#pragma unroll
    for (int o = 16; o; o >>= 1) {
        l0 += __shfl_xor_sync(0xffffffffu, l0, o);
        l1 += __shfl_xor_sync(0xffffffffu, l1, o);
        l2 += __shfl_xor_sync(0xffffffffu, l2, o);
        l3 += __shfl_xor_sync(0xffffffffu, l3, o);
    }
    __shared__ float lr[8][4];
    if (lane == 0) { lr[warp][0] = l0; lr[warp][1] = l1; lr[warp][2] = l2; lr[warp][3] = l3; }
    __syncthreads();
    if (t == 0) {
        float L[NE];
#pragma unroll
        for (int e = 0; e < NE; e++) {
            float a = gate_b[e];
#pragma unroll
            for (int wg = 0; wg < 8; wg++) a += lr[wg][e];
            L[e] = a;
        }
        float m = L[0];
#pragma unroll
        for (int e = 1; e < NE; e++) m = fmaxf(m, L[e]);
        float sum = 0.f, ew[NE];
#pragma unroll
        for (int e = 0; e < NE; e++) { ew[e] = expf(L[e] - m); sum += ew[e]; }
        const float inv = 1.0f / sum;
#pragma unroll
        for (int e = 0; e < NE; e++) g_gate[row * NE + e] = ew[e] * inv;
        // initialize output with gated b2 bias (also clears 0xAA poison)
#pragma unroll
        for (int c = 0; c < NC; c++) {
            float a = 0.f;
#pragma unroll
            for (int e = 0; e < NE; e++) a += ew[e] * inv * ex_b2[e * NC + c];
            out[row * NC + c] = a;
        }
    }
}

// ========================= Kernel 2: fused expert MLP (the GEMM) ==================
// D[B,1024] x w1[1024,2048] -> GELU -> x w2[2048,3], gated-accumulated into out.
// Grid: (token tiles, H splits, experts). H contraction fused: h never hits memory.
__global__ __launch_bounds__(256) void expert_kernel(
    const float* __restrict__ ex_ln_g, const float* __restrict__ ex_ln_b,
    const float* __restrict__ ex_w1,   const float* __restrict__ ex_b1,
    const float* __restrict__ ex_w2,   float* __restrict__ out)
{
    __shared__ float As[BK][132];   // transposed A tile (pad vs store conflicts)
    __shared__ float Bs[BK][BN];

    const int tb   = blockIdx.x;
    const int hs   = blockIdx.y;
    const int e    = blockIdx.z;
    const int row0 = tb * BM;
    const int t    = threadIdx.x;
    const int tx   = t & 15, ty = t >> 4;

    // tile-load indices
    const int ar = t >> 2;          // 0..63  (A row, +64 for 2nd half)
    const int ac = (t & 3) * 4;     // A col group (0,4,8,12)
    const int bk = t >> 5;          // 0..7   (B row, +8 for 2nd half)
    const int bn = (t & 31) * 4;    // B col

    const size_t w1_base = (size_t)e * DIM * HID;

    float outacc[8][NC];
#pragma unroll
    for (int i = 0; i < 8; i++)
#pragma unroll
        for (int c = 0; c < NC; c++) outacc[i][c] = 0.f;

    for (int nt = 0; nt < NT_PER_SPLIT; nt++) {
        const int n0 = (hs * NT_PER_SPLIT + nt) * BN;

        unsigned long long acc[4][8];   // packed row-pairs x 8 cols
#pragma unroll
        for (int i = 0; i < 4; i++)
#pragma unroll
            for (int j = 0; j < 8; j++) acc[i][j] = 0ull;

        float4 An[2], Ag[2], Ab[2], Bw[2];
        // prologue load (register double-buffer of gmem tile)
        {
            const int k0 = 0;
#pragma unroll
            for (int h = 0; h < 2; h++) {
                const int r = ar + h * 64;
                An[h] = *(const float4*)(g_normed + (size_t)(row0 + r) * DIM + k0 + ac);
                Ag[h] = *(const float4*)(ex_ln_g + e * DIM + k0 + ac);
                Ab[h] = *(const float4*)(ex_ln_b + e * DIM + k0 + ac);
                const int k = bk + h * 8;
                Bw[h] = *(const float4*)(ex_w1 + w1_base + (size_t)(k0 + k) * HID + n0 + bn);
            }
        }

        for (int kt = 0; kt < KT; kt++) {
            // commit current tile to smem
#pragma unroll
            for (int h = 0; h < 2; h++) {
                const int r = ar + h * 64;
                As[ac + 0][r] = fmaf(An[h].x, Ag[h].x, Ab[h].x);
                As[ac + 1][r] = fmaf(An[h].y, Ag[h].y, Ab[h].y);
                As[ac + 2][r] = fmaf(An[h].z, Ag[h].z, Ab[h].z);
                As[ac + 3][r] = fmaf(An[h].w, Ag[h].w, Ab[h].w);
                const int k = bk + h * 8;
                *(float4*)&Bs[k][bn] = Bw[h];
            }
            __syncthreads();

            // prefetch next tile while computing
            if (kt + 1 < KT) {
                const int k0 = (kt + 1) * BK;
#pragma unroll
                for (int h = 0; h < 2; h++) {
                    const int r = ar + h * 64;
                    An[h] = *(const float4*)(g_normed + (size_t)(row0 + r) * DIM + k0 + ac);
                    Ag[h] = *(const float4*)(ex_ln_g + e * DIM + k0 + ac);
                    Ab[h] = *(const float4*)(ex_ln_b + e * DIM + k0 + ac);
                    const int k = bk + h * 8;
                    Bw[h] = *(const float4*)(ex_w1 + w1_base + (size_t)(k0 + k) * HID + n0 + bn);
                }
            }

#pragma unroll
            for (int k = 0; k < BK; k++) {
                // row-pairs come packed straight from smem (little-endian float pairs)
                const ulonglong2 a01 = *(const ulonglong2*)&As[k][ty * 8];
                const ulonglong2 a23 = *(const ulonglong2*)&As[k][ty * 8 + 4];
                const float4 b0 = *(const float4*)&Bs[k][tx * 4];
                const float4 b1 = *(const float4*)&Bs[k][64 + tx * 4];
                unsigned long long ap[4] = { a01.x, a01.y, a23.x, a23.y };
                unsigned long long bd[8] = {
                    pk2(b0.x, b0.x), pk2(b0.y, b0.y), pk2(b0.z, b0.z), pk2(b0.w, b0.w),
                    pk2(b1.x, b1.x), pk2(b1.y, b1.y), pk2(b1.z, b1.z), pk2(b1.w, b1.w)
                };
#pragma unroll
                for (int i = 0; i < 4; i++)
#pragma unroll
                    for (int j = 0; j < 8; j++) fma2(acc[i][j], ap[i], bd[j]);
            }
            __syncthreads();
        }

        // epilogue: +b1, GELU, contract with w2[col][0..2] into per-row partials
#pragma unroll
        for (int jj = 0; jj < 8; jj++) {
            const int col = (jj < 4) ? (n0 + tx * 4 + jj) : (n0 + 64 + tx * 4 + (jj - 4));
            const float b1v = ex_b1[e * HID + col];
            const size_t w2o = ((size_t)e * HID + col) * NC;
            const float w2a = ex_w2[w2o + 0];
            const float w2b = ex_w2[w2o + 1];
            const float w2c = ex_w2[w2o + 2];
#pragma unroll
            for (int i2 = 0; i2 < 4; i2++) {
                const float2 h2 = upk2(acc[i2][jj]);
                const float ha = gelu_exact(h2.x + b1v);
                const float hb = gelu_exact(h2.y + b1v);
                outacc[2 * i2 + 0][0] += ha * w2a;
                outacc[2 * i2 + 0][1] += ha * w2b;
                outacc[2 * i2 + 0][2] += ha * w2c;
                outacc[2 * i2 + 1][0] += hb * w2a;
                outacc[2 * i2 + 1][1] += hb * w2b;
                outacc[2 * i2 + 1][2] += hb * w2c;
            }
        }
    }

    // cross-lane reduce over the 16 tx lanes (same ty share rows), gated atomic add
#pragma unroll
    for (int ii = 0; ii < 8; ii++) {
        const int row = row0 + ty * 8 + ii;
        const float gw = g_gate[row * NE + e];
#pragma unroll
        for (int c = 0; c < NC; c++) {
            float v = outacc[ii][c];
            v += __shfl_xor_sync(0xffffffffu, v, 8);
            v += __shfl_xor_sync(0xffffffffu, v, 4);
            v += __shfl_xor_sync(0xffffffffu, v, 2);
            v += __shfl_xor_sync(0xffffffffu, v, 1);
            if (tx == 0) atomicAdd(&out[row * NC + c], gw * v);
        }
    }
}

// ==================================================================================
extern "C" void kernel_launch(void* const* d_in, const int* in_sizes, int n_in,
                              void* d_out, int out_size)
{
    const float* x       = (const float*)d_in[0];
    const float* gln_g   = (const float*)d_in[1];
    const float* gln_b   = (const float*)d_in[2];
    const float* gate_w  = (const float*)d_in[3];
    const float* gate_b  = (const float*)d_in[4];
    const float* ex_ln_g = (const float*)d_in[5];
    const float* ex_ln_b = (const float*)d_in[6];
    const float* ex_w1   = (const float*)d_in[7];
    const float* ex_b1   = (const float*)d_in[8];
    const float* ex_w2   = (const float*)d_in[9];
    const float* ex_b2   = (const float*)d_in[10];
    float* out = (float*)d_out;

    ln_gate_kernel<<<B_TOK, 256>>>(x, gln_g, gln_b, gate_w, gate_b, ex_b2, out);

    dim3 grid(B_TOK / BM, NSPLIT, NE);
    expert_kernel<<<grid, 256>>>(ex_ln_g, ex_ln_b, ex_w1, ex_b1, ex_w2, out);
}

// round 5
// speedup vs baseline: 6.2667x; 6.2667x over previous
#include <cuda_runtime.h>
#include <cuda_fp16.h>
#include <math.h>
#include <stdint.h>

#define B_TOK 16384
#define DIM   1024          // K
#define HID   2048
#define NE    4
#define NC    3
#define NTOT  (NE * HID)    // 8192 rows of folded W1 (N dimension)

#define BM 128
#define BN 128
#define BK 32               // 32 halfs = 64B per row
#define KITERS (DIM / BK)   // 32
#define STAGES 4
#define ASTG 8192           // A stage bytes: 128*32*2
#define BSTG 8192
#define STG  (ASTG + BSTG)  // 16 KB / stage
#define DYN_SMEM (STAGES * STG)  // 64 KB

// ---- device scratch (allocation-free) ----
__device__ __align__(1024) __half g_normed_h[(size_t)B_TOK * DIM];  // 32 MB
__device__ __align__(1024) __half g_w1h[(size_t)NTOT * DIM];        // 16 MB (K-major, g-folded)
__device__ __align__(1024) float  g_b1f[NTOT];                      // b1 + lnb@w1
__device__ __align__(1024) float  g_gate[B_TOK * NE];

// ============================ PTX helpers (sm_80-safe only) ============================
__device__ __forceinline__ uint32_t smem_u32(const void* p) {
    uint32_t a;
    asm("{ .reg .u64 t; cvta.to.shared.u64 t, %1; cvt.u32.u64 %0, t; }" : "=r"(a) : "l"(p));
    return a;
}
__device__ __forceinline__ void cp16(uint32_t sa, const void* g) {
    asm volatile("cp.async.cg.shared.global [%0], [%1], 16;" :: "r"(sa), "l"(g) : "memory");
}
#define CP_COMMIT() asm volatile("cp.async.commit_group;" ::: "memory")
#define CP_WAIT(n)  asm volatile("cp.async.wait_group %0;" :: "n"(n) : "memory")

#define LDSM4(r, a) \
    asm volatile("ldmatrix.sync.aligned.m8n8.x4.shared.b16 {%0,%1,%2,%3}, [%4];" \
        : "=r"((r)[0]), "=r"((r)[1]), "=r"((r)[2]), "=r"((r)[3]) : "r"(a))

#define MMA16816(d, a, b) \
    asm volatile("mma.sync.aligned.m16n8k16.row.col.f32.f16.f16.f32 " \
        "{%0,%1,%2,%3}, {%4,%5,%6,%7}, {%8,%9}, {%0,%1,%2,%3};" \
        : "+f"((d)[0]), "+f"((d)[1]), "+f"((d)[2]), "+f"((d)[3]) \
        : "r"((a)[0]), "r"((a)[1]), "r"((a)[2]), "r"((a)[3]), "r"((b)[0]), "r"((b)[1]))

__device__ __forceinline__ float gelu_exact(float v) {
    return 0.5f * v * (1.0f + erff(v * 0.70710678118654752f));
}

// ============== K0: LayerNorm + gate softmax + out bias init ==============
__global__ __launch_bounds__(256) void ln_gate_kernel(
    const float* __restrict__ x,
    const float* __restrict__ gln_g, const float* __restrict__ gln_b,
    const float* __restrict__ gate_w, const float* __restrict__ gate_b,
    const float* __restrict__ ex_b2, float* __restrict__ out)
{
    const int row = blockIdx.x, t = threadIdx.x;
    const int lane = t & 31, warp = t >> 5;

    const float4 xv = *(const float4*)(x + (size_t)row * DIM + t * 4);
    float s  = xv.x + xv.y + xv.z + xv.w;
    float ss = xv.x * xv.x + xv.y * xv.y + xv.z * xv.z + xv.w * xv.w;
#pragma unroll
    for (int o = 16; o; o >>= 1) {
        s  += __shfl_xor_sync(0xffffffffu, s, o);
        ss += __shfl_xor_sync(0xffffffffu, ss, o);
    }
    __shared__ float rs[8], rss[8];
    if (lane == 0) { rs[warp] = s; rss[warp] = ss; }
    __syncthreads();
    s = 0.f; ss = 0.f;
#pragma unroll
    for (int w = 0; w < 8; w++) { s += rs[w]; ss += rss[w]; }
    const float mu = s * (1.0f / DIM);
    const float var = ss * (1.0f / DIM) - mu * mu;
    const float rstd = rsqrtf(var + 1e-5f);

    float4 nv;
    nv.x = (xv.x - mu) * rstd; nv.y = (xv.y - mu) * rstd;
    nv.z = (xv.z - mu) * rstd; nv.w = (xv.w - mu) * rstd;
    // fp16 copy for the tensor-core GEMM
    __half2* np = (__half2*)(g_normed_h + (size_t)row * DIM + t * 4);
    np[0] = __floats2half2_rn(nv.x, nv.y);
    np[1] = __floats2half2_rn(nv.z, nv.w);

    const int d0 = t * 4;
    const float4 gg = *(const float4*)(gln_g + d0);
    const float4 gb = *(const float4*)(gln_b + d0);
    float y0 = fmaf(nv.x, gg.x, gb.x), y1 = fmaf(nv.y, gg.y, gb.y);
    float y2 = fmaf(nv.z, gg.z, gb.z), y3 = fmaf(nv.w, gg.w, gb.w);
    float l0 = 0.f, l1 = 0.f, l2 = 0.f, l3 = 0.f;
    float4 w;
    w = *(const float4*)(gate_w + (size_t)(d0 + 0) * NE);
    l0 += y0 * w.x; l1 += y0 * w.y; l2 += y0 * w.z; l3 += y0 * w.w;
    w = *(const float4*)(gate_w + (size_t)(d0 + 1) * NE);
    l0 += y1 * w.x; l1 += y1 * w.y; l2 += y1 * w.z; l3 += y1 * w.w;
    w = *(const float4*)(gate_w + (size_t)(d0 + 2) * NE);
    l0 += y2 * w.x; l1 += y2 * w.y; l2 += y2 * w.z; l3 += y2 * w.w;
    w = *(const float4*)(gate_w + (size_t)(d0 + 3) * NE);
    l0 += y3 * w.x; l1 += y3 * w.y; l2 += y3 * w.z; l3 += y3 * w.w;
#pragma unroll
    for (int o = 16; o; o >>= 1) {
        l0 += __shfl_xor_sync(0xffffffffu, l0, o);
        l1 += __shfl_xor_sync(0xffffffffu, l1, o);
        l2 += __shfl_xor_sync(0xffffffffu, l2, o);
        l3 += __shfl_xor_sync(0xffffffffu, l3, o);
    }
    __shared__ float lr[8][4];
    if (lane == 0) { lr[warp][0] = l0; lr[warp][1] = l1; lr[warp][2] = l2; lr[warp][3] = l3; }
    __syncthreads();
    if (t == 0) {
        float L[NE];
#pragma unroll
        for (int e = 0; e < NE; e++) {
            float a = gate_b[e];
#pragma unroll
            for (int wg = 0; wg < 8; wg++) a += lr[wg][e];
            L[e] = a;
        }
        float m = L[0];
#pragma unroll
        for (int e = 1; e < NE; e++) m = fmaxf(m, L[e]);
        float sum = 0.f, ew[NE];
#pragma unroll
        for (int e = 0; e < NE; e++) { ew[e] = expf(L[e] - m); sum += ew[e]; }
        const float inv = 1.0f / sum;
#pragma unroll
        for (int e = 0; e < NE; e++) g_gate[row * NE + e] = ew[e] * inv;
#pragma unroll
        for (int c = 0; c < NC; c++) {
            float a = 0.f;
#pragma unroll
            for (int e = 0; e < NE; e++) a += ew[e] * inv * ex_b2[e * NC + c];
            out[row * NC + c] = a;
        }
    }
}

// ===== K1: fold ln gain into w1, transpose to [e*H+h][d] K-major, cast fp16 =====
__global__ __launch_bounds__(256) void fold_w1_kernel(
    const float* __restrict__ w1, const float* __restrict__ lng)
{
    __shared__ float tile[32][33];
    const int tx = threadIdx.x, ty = threadIdx.y;
    const int h0 = blockIdx.x * 32, d0 = blockIdx.y * 32, e = blockIdx.z;
#pragma unroll
    for (int i = 0; i < 4; i++) {
        const int d = d0 + ty + i * 8;
        tile[ty + i * 8][tx] = w1[((size_t)e * DIM + d) * HID + h0 + tx] * lng[e * DIM + d];
    }
    __syncthreads();
#pragma unroll
    for (int i = 0; i < 4; i++) {
        const int h = h0 + ty + i * 8;
        g_w1h[((size_t)e * HID + h) * DIM + d0 + tx] = __float2half_rn(tile[tx][ty + i * 8]);
    }
}

// ===== K2: b1f[e][h] = b1[e][h] + sum_d lnb[e][d] * w1[e][d][h] =====
__global__ __launch_bounds__(256) void fold_b1_kernel(
    const float* __restrict__ w1, const float* __restrict__ lnb,
    const float* __restrict__ b1)
{
    const int e = blockIdx.y;
    const int h = blockIdx.x * 256 + threadIdx.x;
    float acc = b1[e * HID + h];
    const float* wp = w1 + (size_t)e * DIM * HID + h;
    const float* bp = lnb + e * DIM;
#pragma unroll 4
    for (int d = 0; d < DIM; d++) acc += bp[d] * wp[(size_t)d * HID];
    g_b1f[e * HID + h] = acc;
}

// ============== K3: mma.sync fp16 GEMM + fused GELU/w2/gate epilogue ==============
__global__ __launch_bounds__(256, 2) void gemm_kernel(
    const float* __restrict__ ex_w2, float* __restrict__ out)
{
    extern __shared__ __align__(1024) char smem[];
    __shared__ float sred[BM * NC];
    const uint32_t sb = smem_u32(smem);
    const int t = threadIdx.x;
    const int warp = t >> 5, lane = t & 31;
    const int row0 = blockIdx.x * BM;
    const int n0 = blockIdx.y * BN;
    const int wm = warp >> 2;      // 0..1 -> 64-row band
    const int wn = warp & 3;       // 0..3 -> 32-col band

    float acc[4][4][4];
#pragma unroll
    for (int mi = 0; mi < 4; mi++)
#pragma unroll
        for (int nf = 0; nf < 4; nf++)
#pragma unroll
            for (int q = 0; q < 4; q++) acc[mi][nf][q] = 0.f;

    // ---- async tile loader: 16B chunks, xor-swizzled (conflict-free ldmatrix) ----
    auto load_stage = [&](int stage, int kc) {
        const int k0 = kc * BK;
        const uint32_t sA = sb + stage * STG;
        const uint32_t sB = sA + ASTG;
#pragma unroll
        for (int j = 0; j < 2; j++) {
            const int idx = t + j * 256;
            const int row = idx >> 2, c = idx & 3;
            const int phys = c ^ ((row >> 1) & 3);
            const uint32_t off = row * 64 + phys * 16;
            cp16(sA + off, g_normed_h + (size_t)(row0 + row) * DIM + k0 + c * 8);
            cp16(sB + off, g_w1h + (size_t)(n0 + row) * DIM + k0 + c * 8);
        }
    };

#pragma unroll
    for (int s = 0; s < STAGES - 1; s++) { load_stage(s, s); CP_COMMIT(); }

    for (int it = 0; it < KITERS; it++) {
        CP_WAIT(STAGES - 2);
        __syncthreads();
        const int nxt = it + STAGES - 1;
        if (nxt < KITERS) load_stage(nxt % STAGES, nxt);
        CP_COMMIT();

        const uint32_t sA = sb + (it % STAGES) * STG;
        const uint32_t sB = sA + ASTG;
#pragma unroll
        for (int ks = 0; ks < 2; ks++) {
            uint32_t a[4][4], bf[4][2];
#pragma unroll
            for (int mi = 0; mi < 4; mi++) {
                const int row = wm * 64 + mi * 16 + (lane & 15);
                const int c = ks * 2 + (lane >> 4);
                const int phys = c ^ ((row >> 1) & 3);
                LDSM4(a[mi], sA + row * 64 + phys * 16);
            }
#pragma unroll
            for (int g = 0; g < 2; g++) {
                const int row = wn * 32 + g * 16 + (lane & 15);
                const int c = ks * 2 + (lane >> 4);
                const int phys = c ^ ((row >> 1) & 3);
                uint32_t r[4];
                LDSM4(r, sB + row * 64 + phys * 16);
                bf[2 * g][0] = r[0];     bf[2 * g][1] = r[2];
                bf[2 * g + 1][0] = r[1]; bf[2 * g + 1][1] = r[3];
            }
#pragma unroll
            for (int mi = 0; mi < 4; mi++)
#pragma unroll
                for (int nf = 0; nf < 4; nf++)
                    MMA16816(acc[mi][nf], a[mi], bf[nf]);
        }
    }
    CP_WAIT(0);

    // ---- epilogue: +b1f, exact GELU, x w2 (H->3), smem row-reduce, gated atomics ----
    const int e = blockIdx.y >> 4;   // expert = n0 / HID
    for (int i = t; i < BM * NC; i += 256) sred[i] = 0.f;
    __syncthreads();

#pragma unroll
    for (int mi = 0; mi < 4; mi++) {
        float s00 = 0.f, s01 = 0.f, s02 = 0.f;   // row (lane>>2)
        float s10 = 0.f, s11 = 0.f, s12 = 0.f;   // row +8
#pragma unroll
        for (int nf = 0; nf < 4; nf++) {
            const int n = n0 + wn * 32 + nf * 8 + (lane & 3) * 2;
            const float b1a = __ldg(&g_b1f[n]), b1b = __ldg(&g_b1f[n + 1]);
            const float wa0 = __ldg(&ex_w2[n * 3 + 0]);
            const float wa1 = __ldg(&ex_w2[n * 3 + 1]);
            const float wa2 = __ldg(&ex_w2[n * 3 + 2]);
            const float wb0 = __ldg(&ex_w2[n * 3 + 3]);
            const float wb1 = __ldg(&ex_w2[n * 3 + 4]);
            const float wb2 = __ldg(&ex_w2[n * 3 + 5]);
            const float v00 = gelu_exact(acc[mi][nf][0] + b1a);
            const float v01 = gelu_exact(acc[mi][nf][1] + b1b);
            const float v10 = gelu_exact(acc[mi][nf][2] + b1a);
            const float v11 = gelu_exact(acc[mi][nf][3] + b1b);
            s00 += v00 * wa0 + v01 * wb0;
            s01 += v00 * wa1 + v01 * wb1;
            s02 += v00 * wa2 + v01 * wb2;
            s10 += v10 * wa0 + v11 * wb0;
            s11 += v10 * wa1 + v11 * wb1;
            s12 += v10 * wa2 + v11 * wb2;
        }
#pragma unroll
        for (int o = 2; o; o >>= 1) {
            s00 += __shfl_xor_sync(0xffffffffu, s00, o);
            s01 += __shfl_xor_sync(0xffffffffu, s01, o);
            s02 += __shfl_xor_sync(0xffffffffu, s02, o);
            s10 += __shfl_xor_sync(0xffffffffu, s10, o);
            s11 += __shfl_xor_sync(0xffffffffu, s11, o);
            s12 += __shfl_xor_sync(0xffffffffu, s12, o);
        }
        if ((lane & 3) == 0) {
            const int rl = wm * 64 + mi * 16 + (lane >> 2);
            atomicAdd(&sred[rl * NC + 0], s00);
            atomicAdd(&sred[rl * NC + 1], s01);
            atomicAdd(&sred[rl * NC + 2], s02);
            atomicAdd(&sred[(rl + 8) * NC + 0], s10);
            atomicAdd(&sred[(rl + 8) * NC + 1], s11);
            atomicAdd(&sred[(rl + 8) * NC + 2], s12);
        }
    }
    __syncthreads();

    if (t < BM) {
        const int row = row0 + t;
        const float gw = g_gate[row * NE + e];
        atomicAdd(&out[row * NC + 0], gw * sred[t * NC + 0]);
        atomicAdd(&out[row * NC + 1], gw * sred[t * NC + 1]);
        atomicAdd(&out[row * NC + 2], gw * sred[t * NC + 2]);
    }
}

// ==================================================================================
extern "C" void kernel_launch(void* const* d_in, const int* in_sizes, int n_in,
                              void* d_out, int out_size)
{
    const float* x       = (const float*)d_in[0];
    const float* gln_g   = (const float*)d_in[1];
    const float* gln_b   = (const float*)d_in[2];
    const float* gate_w  = (const float*)d_in[3];
    const float* gate_b  = (const float*)d_in[4];
    const float* ex_ln_g = (const float*)d_in[5];
    const float* ex_ln_b = (const float*)d_in[6];
    const float* ex_w1   = (const float*)d_in[7];
    const float* ex_b1   = (const float*)d_in[8];
    const float* ex_w2   = (const float*)d_in[9];
    const float* ex_b2   = (const float*)d_in[10];
    float* out = (float*)d_out;

    cudaFuncSetAttribute(gemm_kernel, cudaFuncAttributeMaxDynamicSharedMemorySize, DYN_SMEM);

    ln_gate_kernel<<<B_TOK, 256>>>(x, gln_g, gln_b, gate_w, gate_b, ex_b2, out);
    fold_w1_kernel<<<dim3(HID / 32, DIM / 32, NE), dim3(32, 8)>>>(ex_w1, ex_ln_g);
    fold_b1_kernel<<<dim3(HID / 256, NE), 256>>>(ex_w1, ex_ln_b, ex_b1);
    gemm_kernel<<<dim3(B_TOK / BM, NTOT / BN), 256, DYN_SMEM>>>(ex_w2, out);
}

// round 7
// speedup vs baseline: 6.6936x; 1.0681x over previous
#include <cuda_runtime.h>
#include <cuda_fp16.h>
#include <math.h>
#include <stdint.h>

#define B_TOK 16384
#define DIM   1024          // K
#define HID   2048
#define NE    4
#define NC    3
#define NTOT  (NE * HID)    // 8192 rows of folded W1 (N dimension)

#define BM 128
#define BN 128
#define BK 32               // 32 halfs = 64B per row
#define KITERS (DIM / BK)   // 32
#define STAGES 4
#define ASTG 8192           // A stage bytes: 128*32*2
#define BSTG 8192
#define STG  (ASTG + BSTG)  // 16 KB / stage
#define DYN_SMEM (STAGES * STG)  // 64 KB

// ---- device scratch (allocation-free) ----
__device__ __align__(1024) __half g_normed_h[(size_t)B_TOK * DIM];  // 32 MB
__device__ __align__(1024) __half g_w1h[(size_t)NTOT * DIM];        // 16 MB (K-major, g-folded)
__device__ __align__(1024) float  g_b1f[NTOT];                      // b1 + lnb@w1
__device__ __align__(1024) float  g_gate[B_TOK * NE];

// ============================ PTX helpers (sm_80-safe only) ============================
__device__ __forceinline__ uint32_t smem_u32(const void* p) {
    uint32_t a;
    asm("{ .reg .u64 t; cvta.to.shared.u64 t, %1; cvt.u32.u64 %0, t; }" : "=r"(a) : "l"(p));
    return a;
}
__device__ __forceinline__ void cp16(uint32_t sa, const void* g) {
    asm volatile("cp.async.cg.shared.global [%0], [%1], 16;" :: "r"(sa), "l"(g) : "memory");
}
#define CP_COMMIT() asm volatile("cp.async.commit_group;" ::: "memory")
#define CP_WAIT(n)  asm volatile("cp.async.wait_group %0;" :: "n"(n) : "memory")

#define LDSM4(r, a) \
    asm volatile("ldmatrix.sync.aligned.m8n8.x4.shared.b16 {%0,%1,%2,%3}, [%4];" \
        : "=r"((r)[0]), "=r"((r)[1]), "=r"((r)[2]), "=r"((r)[3]) : "r"(a))

#define MMA16816(d, a, b) \
    asm volatile("mma.sync.aligned.m16n8k16.row.col.f32.f16.f16.f32 " \
        "{%0,%1,%2,%3}, {%4,%5,%6,%7}, {%8,%9}, {%0,%1,%2,%3};" \
        : "+f"((d)[0]), "+f"((d)[1]), "+f"((d)[2]), "+f"((d)[3]) \
        : "r"((a)[0]), "r"((a)[1]), "r"((a)[2]), "r"((a)[3]), "r"((b)[0]), "r"((b)[1]))

__device__ __forceinline__ float gelu_exact(float v) {
    return 0.5f * v * (1.0f + erff(v * 0.70710678118654752f));
}

// ============== K0: LayerNorm + gate softmax + out bias init ==============
__global__ __launch_bounds__(256) void ln_gate_kernel(
    const float* __restrict__ x,
    const float* __restrict__ gln_g, const float* __restrict__ gln_b,
    const float* __restrict__ gate_w, const float* __restrict__ gate_b,
    const float* __restrict__ ex_b2, float* __restrict__ out)
{
    const int row = blockIdx.x, t = threadIdx.x;
    const int lane = t & 31, warp = t >> 5;

    const float4 xv = *(const float4*)(x + (size_t)row * DIM + t * 4);
    float s  = xv.x + xv.y + xv.z + xv.w;
    float ss = xv.x * xv.x + xv.y * xv.y + xv.z * xv.z + xv.w * xv.w;
#pragma unroll
    for (int o = 16; o; o >>= 1) {
        s  += __shfl_xor_sync(0xffffffffu, s, o);
        ss += __shfl_xor_sync(0xffffffffu, ss, o);
    }
    __shared__ float rs[8], rss[8];
    if (lane == 0) { rs[warp] = s; rss[warp] = ss; }
    __syncthreads();
    s = 0.f; ss = 0.f;
#pragma unroll
    for (int w = 0; w < 8; w++) { s += rs[w]; ss += rss[w]; }
    const float mu = s * (1.0f / DIM);
    const float var = ss * (1.0f / DIM) - mu * mu;
    const float rstd = rsqrtf(var + 1e-5f);

    float4 nv;
    nv.x = (xv.x - mu) * rstd; nv.y = (xv.y - mu) * rstd;
    nv.z = (xv.z - mu) * rstd; nv.w = (xv.w - mu) * rstd;
    __half2* np = (__half2*)(g_normed_h + (size_t)row * DIM + t * 4);
    np[0] = __floats2half2_rn(nv.x, nv.y);
    np[1] = __floats2half2_rn(nv.z, nv.w);

    const int d0 = t * 4;
    const float4 gg = *(const float4*)(gln_g + d0);
    const float4 gb = *(const float4*)(gln_b + d0);
    float y0 = fmaf(nv.x, gg.x, gb.x), y1 = fmaf(nv.y, gg.y, gb.y);
    float y2 = fmaf(nv.z, gg.z, gb.z), y3 = fmaf(nv.w, gg.w, gb.w);
    float l0 = 0.f, l1 = 0.f, l2 = 0.f, l3 = 0.f;
    float4 w;
    w = *(const float4*)(gate_w + (size_t)(d0 + 0) * NE);
    l0 += y0 * w.x; l1 += y0 * w.y; l2 += y0 * w.z; l3 += y0 * w.w;
    w = *(const float4*)(gate_w + (size_t)(d0 + 1) * NE);
    l0 += y1 * w.x; l1 += y1 * w.y; l2 += y1 * w.z; l3 += y1 * w.w;
    w = *(const float4*)(gate_w + (size_t)(d0 + 2) * NE);
    l0 += y2 * w.x; l1 += y2 * w.y; l2 += y2 * w.z; l3 += y2 * w.w;
    w = *(const float4*)(gate_w + (size_t)(d0 + 3) * NE);
    l0 += y3 * w.x; l1 += y3 * w.y; l2 += y3 * w.z; l3 += y3 * w.w;
#pragma unroll
    for (int o = 16; o; o >>= 1) {
        l0 += __shfl_xor_sync(0xffffffffu, l0, o);
        l1 += __shfl_xor_sync(0xffffffffu, l1, o);
        l2 += __shfl_xor_sync(0xffffffffu, l2, o);
        l3 += __shfl_xor_sync(0xffffffffu, l3, o);
    }
    __shared__ float lr[8][4];
    if (lane == 0) { lr[warp][0] = l0; lr[warp][1] = l1; lr[warp][2] = l2; lr[warp][3] = l3; }
    __syncthreads();
    if (t == 0) {
        float L[NE];
#pragma unroll
        for (int e = 0; e < NE; e++) {
            float a = gate_b[e];
#pragma unroll
            for (int wg = 0; wg < 8; wg++) a += lr[wg][e];
            L[e] = a;
        }
        float m = L[0];
#pragma unroll
        for (int e = 1; e < NE; e++) m = fmaxf(m, L[e]);
        float sum = 0.f, ew[NE];
#pragma unroll
        for (int e = 0; e < NE; e++) { ew[e] = expf(L[e] - m); sum += ew[e]; }
        const float inv = 1.0f / sum;
#pragma unroll
        for (int e = 0; e < NE; e++) g_gate[row * NE + e] = ew[e] * inv;
#pragma unroll
        for (int c = 0; c < NC; c++) {
            float a = 0.f;
#pragma unroll
            for (int e = 0; e < NE; e++) a += ew[e] * inv * ex_b2[e * NC + c];
            out[row * NC + c] = a;
        }
    }
}

// ===== K1: fold ln gain into w1, transpose to [e*H+h][d] K-major, cast fp16 =====
__global__ __launch_bounds__(256) void fold_w1_kernel(
    const float* __restrict__ w1, const float* __restrict__ lng)
{
    __shared__ float tile[32][33];
    const int tx = threadIdx.x, ty = threadIdx.y;
    const int h0 = blockIdx.x * 32, d0 = blockIdx.y * 32, e = blockIdx.z;
#pragma unroll
    for (int i = 0; i < 4; i++) {
        const int d = d0 + ty + i * 8;
        tile[ty + i * 8][tx] = w1[((size_t)e * DIM + d) * HID + h0 + tx] * lng[e * DIM + d];
    }
    __syncthreads();
#pragma unroll
    for (int i = 0; i < 4; i++) {
        const int h = h0 + ty + i * 8;
        g_w1h[((size_t)e * HID + h) * DIM + d0 + tx] = __float2half_rn(tile[tx][ty + i * 8]);
    }
}

// ===== K2: b1f[e][h] = b1[e][h] + sum_d lnb[e][d] * w1[e][d][h] =====
__global__ __launch_bounds__(256) void fold_b1_kernel(
    const float* __restrict__ w1, const float* __restrict__ lnb,
    const float* __restrict__ b1)
{
    const int e = blockIdx.y;
    const int h = blockIdx.x * 256 + threadIdx.x;
    float acc = b1[e * HID + h];
    const float* wp = w1 + (size_t)e * DIM * HID + h;
    const float* bp = lnb + e * DIM;
#pragma unroll 4
    for (int d = 0; d < DIM; d++) acc += bp[d] * wp[(size_t)d * HID];
    g_b1f[e * HID + h] = acc;
}

// ============== K3: mma.sync fp16 GEMM + fused GELU/w2/gate epilogue ==============
// All smem addressing hoisted out of the k-loop: loader smem offsets are
// per-thread constants (gmem pointers bump by 64B/chunk); the 12 ldmatrix
// source offsets (swizzle included) are loop-invariant.
__global__ __launch_bounds__(256, 2) void gemm_kernel(
    const float* __restrict__ ex_w2, float* __restrict__ out)
{
    extern __shared__ __align__(1024) char smem[];
    __shared__ float sred[BM * NC];
    const uint32_t sb = smem_u32(smem);
    const int t = threadIdx.x;
    const int warp = t >> 5, lane = t & 31;
    const int row0 = blockIdx.x * BM;
    const int n0 = blockIdx.y * BN;
    const int wm = warp >> 2;      // 0..1 -> 64-row band
    const int wn = warp & 3;       // 0..3 -> 32-col band

    float acc[4][4][4];
#pragma unroll
    for (int mi = 0; mi < 4; mi++)
#pragma unroll
        for (int nf = 0; nf < 4; nf++)
#pragma unroll
            for (int q = 0; q < 4; q++) acc[mi][nf][q] = 0.f;

    // ---- loader constants: smem dst offsets fixed; gmem pointers bump 64B/chunk ----
    const int lrow0 = t >> 2, lc0 = t & 3;
    const int lrow1 = (t + 256) >> 2, lc1 = (t + 256) & 3;
    const uint32_t ldst0 = lrow0 * 64 + (lc0 ^ ((lrow0 >> 1) & 3)) * 16;
    const uint32_t ldst1 = lrow1 * 64 + (lc1 ^ ((lrow1 >> 1) & 3)) * 16;
    const char* gA0 = (const char*)(g_normed_h + (size_t)(row0 + lrow0) * DIM + lc0 * 8);
    const char* gA1 = (const char*)(g_normed_h + (size_t)(row0 + lrow1) * DIM + lc1 * 8);
    const char* gB0 = (const char*)(g_w1h + (size_t)(n0 + lrow0) * DIM + lc0 * 8);
    const char* gB1 = (const char*)(g_w1h + (size_t)(n0 + lrow1) * DIM + lc1 * 8);

    // ---- ldmatrix source offsets (loop-invariant, swizzle baked in) ----
    uint32_t aoff[2][4], boff[2][2];
#pragma unroll
    for (int ks = 0; ks < 2; ks++) {
        const int c = ks * 2 + (lane >> 4);
#pragma unroll
        for (int mi = 0; mi < 4; mi++) {
            const int row = wm * 64 + mi * 16 + (lane & 15);
            aoff[ks][mi] = row * 64 + (c ^ ((row >> 1) & 3)) * 16;
        }
#pragma unroll
        for (int g = 0; g < 2; g++) {
            const int row = wn * 32 + g * 16 + (lane & 15);
            boff[ks][g] = ASTG + row * 64 + (c ^ ((row >> 1) & 3)) * 16;
        }
    }

    // ---- prologue: fill STAGES-1 stages ----
#pragma unroll
    for (int s = 0; s < STAGES - 1; s++) {
        const uint32_t sbase = sb + s * STG;
        cp16(sbase + ldst0, gA0); cp16(sbase + ASTG + ldst0, gB0);
        cp16(sbase + ldst1, gA1); cp16(sbase + ASTG + ldst1, gB1);
        gA0 += 64; gA1 += 64; gB0 += 64; gB1 += 64;
        CP_COMMIT();
    }

    for (int it = 0; it < KITERS; it++) {
        CP_WAIT(STAGES - 2);
        __syncthreads();
        if (it + STAGES - 1 < KITERS) {
            const uint32_t sbase = sb + ((it + STAGES - 1) & 3) * STG;
            cp16(sbase + ldst0, gA0); cp16(sbase + ASTG + ldst0, gB0);
            cp16(sbase + ldst1, gA1); cp16(sbase + ASTG + ldst1, gB1);
            gA0 += 64; gA1 += 64; gB0 += 64; gB1 += 64;
        }
        CP_COMMIT();

        const uint32_t sS = sb + (it & 3) * STG;
#pragma unroll
        for (int ks = 0; ks < 2; ks++) {
            uint32_t a[4][4], bf[4][2];
#pragma unroll
            for (int mi = 0; mi < 4; mi++) LDSM4(a[mi], sS + aoff[ks][mi]);
#pragma unroll
            for (int g = 0; g < 2; g++) {
                uint32_t r[4];
                LDSM4(r, sS + boff[ks][g]);
                bf[2 * g][0] = r[0];     bf[2 * g][1] = r[2];
                bf[2 * g + 1][0] = r[1]; bf[2 * g + 1][1] = r[3];
            }
#pragma unroll
            for (int mi = 0; mi < 4; mi++)
#pragma unroll
                for (int nf = 0; nf < 4; nf++)
                    MMA16816(acc[mi][nf], a[mi], bf[nf]);
        }
    }
    CP_WAIT(0);

    // ---- epilogue: +b1f, exact GELU, x w2 (H->3), smem row-reduce, gated atomics ----
    const int e = blockIdx.y >> 4;   // expert = n0 / HID
    for (int i = t; i < BM * NC; i += 256) sred[i] = 0.f;
    __syncthreads();

#pragma unroll
    for (int mi = 0; mi < 4; mi++) {
        float s00 = 0.f, s01 = 0.f, s02 = 0.f;
        float s10 = 0.f, s11 = 0.f, s12 = 0.f;
#pragma unroll
        for (int nf = 0; nf < 4; nf++) {
            const int n = n0 + wn * 32 + nf * 8 + (lane & 3) * 2;
            const float b1a = __ldg(&g_b1f[n]), b1b = __ldg(&g_b1f[n + 1]);
            const float wa0 = __ldg(&ex_w2[n * 3 + 0]);
            const float wa1 = __ldg(&ex_w2[n * 3 + 1]);
            const float wa2 = __ldg(&ex_w2[n * 3 + 2]);
            const float wb0 = __ldg(&ex_w2[n * 3 + 3]);
            const float wb1 = __ldg(&ex_w2[n * 3 + 4]);
            const float wb2 = __ldg(&ex_w2[n * 3 + 5]);
            const float v00 = gelu_exact(acc[mi][nf][0] + b1a);
            const float v01 = gelu_exact(acc[mi][nf][1] + b1b);
            const float v10 = gelu_exact(acc[mi][nf][2] + b1a);
            const float v11 = gelu_exact(acc[mi][nf][3] + b1b);
            s00 += v00 * wa0 + v01 * wb0;
            s01 += v00 * wa1 + v01 * wb1;
            s02 += v00 * wa2 + v01 * wb2;
            s10 += v10 * wa0 + v11 * wb0;
            s11 += v10 * wa1 + v11 * wb1;
            s12 += v10 * wa2 + v11 * wb2;
        }
#pragma unroll
        for (int o = 2; o; o >>= 1) {
            s00 += __shfl_xor_sync(0xffffffffu, s00, o);
            s01 += __shfl_xor_sync(0xffffffffu, s01, o);
            s02 += __shfl_xor_sync(0xffffffffu, s02, o);
            s10 += __shfl_xor_sync(0xffffffffu, s10, o);
            s11 += __shfl_xor_sync(0xffffffffu, s11, o);
            s12 += __shfl_xor_sync(0xffffffffu, s12, o);
        }
        if ((lane & 3) == 0) {
            const int rl = wm * 64 + mi * 16 + (lane >> 2);
            atomicAdd(&sred[rl * NC + 0], s00);
            atomicAdd(&sred[rl * NC + 1], s01);
            atomicAdd(&sred[rl * NC + 2], s02);
            atomicAdd(&sred[(rl + 8) * NC + 0], s10);
            atomicAdd(&sred[(rl + 8) * NC + 1], s11);
            atomicAdd(&sred[(rl + 8) * NC + 2], s12);
        }
    }
    __syncthreads();

    if (t < BM) {
        const int row = row0 + t;
        const float gw = g_gate[row * NE + e];
        atomicAdd(&out[row * NC + 0], gw * sred[t * NC + 0]);
        atomicAdd(&out[row * NC + 1], gw * sred[t * NC + 1]);
        atomicAdd(&out[row * NC + 2], gw * sred[t * NC + 2]);
    }
}

// ==================================================================================
extern "C" void kernel_launch(void* const* d_in, const int* in_sizes, int n_in,
                              void* d_out, int out_size)
{
    const float* x       = (const float*)d_in[0];
    const float* gln_g   = (const float*)d_in[1];
    const float* gln_b   = (const float*)d_in[2];
    const float* gate_w  = (const float*)d_in[3];
    const float* gate_b  = (const float*)d_in[4];
    const float* ex_ln_g = (const float*)d_in[5];
    const float* ex_ln_b = (const float*)d_in[6];
    const float* ex_w1   = (const float*)d_in[7];
    const float* ex_b1   = (const float*)d_in[8];
    const float* ex_w2   = (const float*)d_in[9];
    const float* ex_b2   = (const float*)d_in[10];
    float* out = (float*)d_out;

    cudaFuncSetAttribute(gemm_kernel, cudaFuncAttributeMaxDynamicSharedMemorySize, DYN_SMEM);

    ln_gate_kernel<<<B_TOK, 256>>>(x, gln_g, gln_b, gate_w, gate_b, ex_b2, out);
    fold_w1_kernel<<<dim3(HID / 32, DIM / 32, NE), dim3(32, 8)>>>(ex_w1, ex_ln_g);
    fold_b1_kernel<<<dim3(HID / 256, NE), 256>>>(ex_w1, ex_ln_b, ex_b1);
    gemm_kernel<<<dim3(B_TOK / BM, NTOT / BN), 256, DYN_SMEM>>>(ex_w2, out);
}

// round 8
// speedup vs baseline: 6.8238x; 1.0194x over previous
#include <cuda_runtime.h>
#include <cuda_fp16.h>
#include <math.h>
#include <stdint.h>

#define B_TOK 16384
#define DIM   1024          // K
#define HID   2048
#define NE    4
#define NC    3
#define NTOT  (NE * HID)    // 8192 rows of folded W1 (N dimension)

#define BM 128
#define BN 128
#define BK 64               // 64 halfs = 128B per row (full SW128 atom)
#define KITERS (DIM / BK)   // 16
#define STAGES 3
#define ASTG 16384          // A stage bytes: 128*64*2
#define STG  (2 * ASTG)     // 32 KB / stage
#define DYN_SMEM (STAGES * STG)  // 96 KB

// ---- device scratch (allocation-free) ----
__device__ __align__(1024) __half g_normed_h[(size_t)B_TOK * DIM];  // 32 MB
__device__ __align__(1024) __half g_w1h[(size_t)NTOT * DIM];        // 16 MB (K-major, g-folded)
__device__ __align__(1024) float  g_b1f[NTOT];                      // b1 + lnb@w1
__device__ __align__(1024) float  g_gate[B_TOK * NE];

// ============================ PTX helpers (sm_80-safe only) ============================
__device__ __forceinline__ uint32_t smem_u32(const void* p) {
    uint32_t a;
    asm("{ .reg .u64 t; cvta.to.shared.u64 t, %1; cvt.u32.u64 %0, t; }" : "=r"(a) : "l"(p));
    return a;
}
__device__ __forceinline__ void cp16(uint32_t sa, const void* g) {
    asm volatile("cp.async.cg.shared.global [%0], [%1], 16;" :: "r"(sa), "l"(g) : "memory");
}
#define CP_COMMIT() asm volatile("cp.async.commit_group;" ::: "memory")
#define CP_WAIT(n)  asm volatile("cp.async.wait_group %0;" :: "n"(n) : "memory")

#define LDSM4(r, a) \
    asm volatile("ldmatrix.sync.aligned.m8n8.x4.shared.b16 {%0,%1,%2,%3}, [%4];" \
        : "=r"((r)[0]), "=r"((r)[1]), "=r"((r)[2]), "=r"((r)[3]) : "r"(a))

#define MMA16816(d, a, b) \
    asm volatile("mma.sync.aligned.m16n8k16.row.col.f32.f16.f16.f32 " \
        "{%0,%1,%2,%3}, {%4,%5,%6,%7}, {%8,%9}, {%0,%1,%2,%3};" \
        : "+f"((d)[0]), "+f"((d)[1]), "+f"((d)[2]), "+f"((d)[3]) \
        : "r"((a)[0]), "r"((a)[1]), "r"((a)[2]), "r"((a)[3]), "r"((b)[0]), "r"((b)[1]))

__device__ __forceinline__ float gelu_exact(float v) {
    return 0.5f * v * (1.0f + erff(v * 0.70710678118654752f));
}

// ============== K0: LayerNorm + gate softmax + out bias init ==============
__global__ __launch_bounds__(256) void ln_gate_kernel(
    const float* __restrict__ x,
    const float* __restrict__ gln_g, const float* __restrict__ gln_b,
    const float* __restrict__ gate_w, const float* __restrict__ gate_b,
    const float* __restrict__ ex_b2, float* __restrict__ out)
{
    const int row = blockIdx.x, t = threadIdx.x;
    const int lane = t & 31, warp = t >> 5;

    const float4 xv = *(const float4*)(x + (size_t)row * DIM + t * 4);
    float s  = xv.x + xv.y + xv.z + xv.w;
    float ss = xv.x * xv.x + xv.y * xv.y + xv.z * xv.z + xv.w * xv.w;
#pragma unroll
    for (int o = 16; o; o >>= 1) {
        s  += __shfl_xor_sync(0xffffffffu, s, o);
        ss += __shfl_xor_sync(0xffffffffu, ss, o);
    }
    __shared__ float rs[8], rss[8];
    if (lane == 0) { rs[warp] = s; rss[warp] = ss; }
    __syncthreads();
    s = 0.f; ss = 0.f;
#pragma unroll
    for (int w = 0; w < 8; w++) { s += rs[w]; ss += rss[w]; }
    const float mu = s * (1.0f / DIM);
    const float var = ss * (1.0f / DIM) - mu * mu;
    const float rstd = rsqrtf(var + 1e-5f);

    float4 nv;
    nv.x = (xv.x - mu) * rstd; nv.y = (xv.y - mu) * rstd;
    nv.z = (xv.z - mu) * rstd; nv.w = (xv.w - mu) * rstd;
    __half2* np = (__half2*)(g_normed_h + (size_t)row * DIM + t * 4);
    np[0] = __floats2half2_rn(nv.x, nv.y);
    np[1] = __floats2half2_rn(nv.z, nv.w);

    const int d0 = t * 4;
    const float4 gg = *(const float4*)(gln_g + d0);
    const float4 gb = *(const float4*)(gln_b + d0);
    float y0 = fmaf(nv.x, gg.x, gb.x), y1 = fmaf(nv.y, gg.y, gb.y);
    float y2 = fmaf(nv.z, gg.z, gb.z), y3 = fmaf(nv.w, gg.w, gb.w);
    float l0 = 0.f, l1 = 0.f, l2 = 0.f, l3 = 0.f;
    float4 w;
    w = *(const float4*)(gate_w + (size_t)(d0 + 0) * NE);
    l0 += y0 * w.x; l1 += y0 * w.y; l2 += y0 * w.z; l3 += y0 * w.w;
    w = *(const float4*)(gate_w + (size_t)(d0 + 1) * NE);
    l0 += y1 * w.x; l1 += y1 * w.y; l2 += y1 * w.z; l3 += y1 * w.w;
    w = *(const float4*)(gate_w + (size_t)(d0 + 2) * NE);
    l0 += y2 * w.x; l1 += y2 * w.y; l2 += y2 * w.z; l3 += y2 * w.w;
    w = *(const float4*)(gate_w + (size_t)(d0 + 3) * NE);
    l0 += y3 * w.x; l1 += y3 * w.y; l2 += y3 * w.z; l3 += y3 * w.w;
#pragma unroll
    for (int o = 16; o; o >>= 1) {
        l0 += __shfl_xor_sync(0xffffffffu, l0, o);
        l1 += __shfl_xor_sync(0xffffffffu, l1, o);
        l2 += __shfl_xor_sync(0xffffffffu, l2, o);
        l3 += __shfl_xor_sync(0xffffffffu, l3, o);
    }
    __shared__ float lr[8][4];
    if (lane == 0) { lr[warp][0] = l0; lr[warp][1] = l1; lr[warp][2] = l2; lr[warp][3] = l3; }
    __syncthreads();
    if (t == 0) {
        float L[NE];
#pragma unroll
        for (int e = 0; e < NE; e++) {
            float a = gate_b[e];
#pragma unroll
            for (int wg = 0; wg < 8; wg++) a += lr[wg][e];
            L[e] = a;
        }
        float m = L[0];
#pragma unroll
        for (int e = 1; e < NE; e++) m = fmaxf(m, L[e]);
        float sum = 0.f, ew[NE];
#pragma unroll
        for (int e = 0; e < NE; e++) { ew[e] = expf(L[e] - m); sum += ew[e]; }
        const float inv = 1.0f / sum;
#pragma unroll
        for (int e = 0; e < NE; e++) g_gate[row * NE + e] = ew[e] * inv;
#pragma unroll
        for (int c = 0; c < NC; c++) {
            float a = 0.f;
#pragma unroll
            for (int e = 0; e < NE; e++) a += ew[e] * inv * ex_b2[e * NC + c];
            out[row * NC + c] = a;
        }
    }
}

// ===== K1: fold ln gain into w1, transpose to [e*H+h][d] K-major, cast fp16 =====
__global__ __launch_bounds__(256) void fold_w1_kernel(
    const float* __restrict__ w1, const float* __restrict__ lng)
{
    __shared__ float tile[32][33];
    const int tx = threadIdx.x, ty = threadIdx.y;
    const int h0 = blockIdx.x * 32, d0 = blockIdx.y * 32, e = blockIdx.z;
#pragma unroll
    for (int i = 0; i < 4; i++) {
        const int d = d0 + ty + i * 8;
        tile[ty + i * 8][tx] = w1[((size_t)e * DIM + d) * HID + h0 + tx] * lng[e * DIM + d];
    }
    __syncthreads();
#pragma unroll
    for (int i = 0; i < 4; i++) {
        const int h = h0 + ty + i * 8;
        g_w1h[((size_t)e * HID + h) * DIM + d0 + tx] = __float2half_rn(tile[tx][ty + i * 8]);
    }
}

// ===== K2: b1f[e][h] = b1[e][h] + sum_d lnb[e][d] * w1[e][d][h] =====
__global__ __launch_bounds__(256) void fold_b1_kernel(
    const float* __restrict__ w1, const float* __restrict__ lnb,
    const float* __restrict__ b1)
{
    const int e = blockIdx.y;
    const int h = blockIdx.x * 256 + threadIdx.x;
    float acc = b1[e * HID + h];
    const float* wp = w1 + (size_t)e * DIM * HID + h;
    const float* bp = lnb + e * DIM;
#pragma unroll 4
    for (int d = 0; d < DIM; d++) acc += bp[d] * wp[(size_t)d * HID];
    g_b1f[e * HID + h] = acc;
}

// ============== K3: mma.sync fp16 GEMM + fused GELU/w2/gate epilogue ==============
// BK=64 (128B rows, swizzle c^(row&7)), 3 stages, 16 outer iters -> half the
// barriers of the BK=32 version. All smem offsets reduce to base regs + immediates
// (row steps of 16/32 preserve row&7, so swizzle is step-invariant).
__global__ __launch_bounds__(256, 2) void gemm_kernel(
    const float* __restrict__ ex_w2, float* __restrict__ out)
{
    extern __shared__ __align__(1024) char smem[];
    __shared__ float sred[BM * NC];
    const uint32_t sb = smem_u32(smem);
    const int t = threadIdx.x;
    const int warp = t >> 5, lane = t & 31;
    const int row0 = blockIdx.x * BM;
    const int n0 = blockIdx.y * BN;
    const int wm = warp >> 2;      // 0..1 -> 64-row band
    const int wn = warp & 3;       // 0..3 -> 32-col band

    float acc[4][4][4];
#pragma unroll
    for (int mi = 0; mi < 4; mi++)
#pragma unroll
        for (int nf = 0; nf < 4; nf++)
#pragma unroll
            for (int q = 0; q < 4; q++) acc[mi][nf][q] = 0.f;

    // ---- loader: thread t handles chunks i = t + 256j (j=0..3) for A and B.
    // row = i>>3 (steps of 32 -> row&7 invariant), c = t&7 for all j.
    const int lrow = t >> 3, lc = t & 7;
    const uint32_t ldst = lrow * 128 + ((lc ^ (lrow & 7)) * 16);   // + j*4096
    const char* gA = (const char*)(g_normed_h + (size_t)(row0 + lrow) * DIM) + lc * 16;
    const char* gB = (const char*)(g_w1h + (size_t)(n0 + lrow) * DIM) + lc * 16;
    // gmem row stride 2048B; j step = 32 rows = 65536B; per-k-iter bump = 128B.

    // ---- ldmatrix base offsets per ks (mi/g add row-steps of 16 -> +2048B immediates) ----
    uint32_t aoff0[4], boff0[4];
    {
        const int arow = wm * 64 + (lane & 15);
        const int brow = wn * 32 + (lane & 15);
        const int hi = lane >> 4;
#pragma unroll
        for (int ks = 0; ks < 4; ks++) {
            const int c = ks * 2 + hi;
            aoff0[ks] = arow * 128 + ((c ^ (arow & 7)) * 16);
            boff0[ks] = ASTG + brow * 128 + ((c ^ (brow & 7)) * 16);
        }
    }

    // ---- prologue: fill STAGES-1 stages ----
#pragma unroll
    for (int s = 0; s < STAGES - 1; s++) {
        const uint32_t sbase = sb + s * STG;
#pragma unroll
        for (int j = 0; j < 4; j++) {
            cp16(sbase + ldst + j * 4096, gA + j * 65536);
            cp16(sbase + ASTG + ldst + j * 4096, gB + j * 65536);
        }
        gA += 128; gB += 128;
        CP_COMMIT();
    }

    int stage = 0, wstage = STAGES - 1;
    for (int it = 0; it < KITERS; it++) {
        CP_WAIT(STAGES - 2);
        __syncthreads();
        if (it + STAGES - 1 < KITERS) {
            const uint32_t sbase = sb + wstage * STG;
#pragma unroll
            for (int j = 0; j < 4; j++) {
                cp16(sbase + ldst + j * 4096, gA + j * 65536);
                cp16(sbase + ASTG + ldst + j * 4096, gB + j * 65536);
            }
            gA += 128; gB += 128;
        }
        CP_COMMIT();
        wstage = (wstage + 1 == STAGES) ? 0 : wstage + 1;

        const uint32_t sS = sb + stage * STG;
        stage = (stage + 1 == STAGES) ? 0 : stage + 1;
#pragma unroll
        for (int ks = 0; ks < 4; ks++) {
            uint32_t a[4][4], bf[4][2];
            const uint32_t ab = sS + aoff0[ks];
            const uint32_t bb = sS + boff0[ks];
#pragma unroll
            for (int mi = 0; mi < 4; mi++) LDSM4(a[mi], ab + mi * 2048);
#pragma unroll
            for (int g = 0; g < 2; g++) {
                uint32_t r[4];
                LDSM4(r, bb + g * 2048);
                bf[2 * g][0] = r[0];     bf[2 * g][1] = r[2];
                bf[2 * g + 1][0] = r[1]; bf[2 * g + 1][1] = r[3];
            }
#pragma unroll
            for (int mi = 0; mi < 4; mi++)
#pragma unroll
                for (int nf = 0; nf < 4; nf++)
                    MMA16816(acc[mi][nf], a[mi], bf[nf]);
        }
    }
    CP_WAIT(0);

    // ---- epilogue: +b1f, exact GELU, x w2 (H->3), smem row-reduce, gated atomics ----
    const int e = blockIdx.y >> 4;   // expert = n0 / HID
    for (int i = t; i < BM * NC; i += 256) sred[i] = 0.f;
    __syncthreads();

#pragma unroll
    for (int mi = 0; mi < 4; mi++) {
        float s00 = 0.f, s01 = 0.f, s02 = 0.f;
        float s10 = 0.f, s11 = 0.f, s12 = 0.f;
#pragma unroll
        for (int nf = 0; nf < 4; nf++) {
            const int n = n0 + wn * 32 + nf * 8 + (lane & 3) * 2;
            const float b1a = __ldg(&g_b1f[n]), b1b = __ldg(&g_b1f[n + 1]);
            const float wa0 = __ldg(&ex_w2[n * 3 + 0]);
            const float wa1 = __ldg(&ex_w2[n * 3 + 1]);
            const float wa2 = __ldg(&ex_w2[n * 3 + 2]);
            const float wb0 = __ldg(&ex_w2[n * 3 + 3]);
            const float wb1 = __ldg(&ex_w2[n * 3 + 4]);
            const float wb2 = __ldg(&ex_w2[n * 3 + 5]);
            const float v00 = gelu_exact(acc[mi][nf][0] + b1a);
            const float v01 = gelu_exact(acc[mi][nf][1] + b1b);
            const float v10 = gelu_exact(acc[mi][nf][2] + b1a);
            const float v11 = gelu_exact(acc[mi][nf][3] + b1b);
            s00 += v00 * wa0 + v01 * wb0;
            s01 += v00 * wa1 + v01 * wb1;
            s02 += v00 * wa2 + v01 * wb2;
            s10 += v10 * wa0 + v11 * wb0;
            s11 += v10 * wa1 + v11 * wb1;
            s12 += v10 * wa2 + v11 * wb2;
        }
#pragma unroll
        for (int o = 2; o; o >>= 1) {
            s00 += __shfl_xor_sync(0xffffffffu, s00, o);
            s01 += __shfl_xor_sync(0xffffffffu, s01, o);
            s02 += __shfl_xor_sync(0xffffffffu, s02, o);
            s10 += __shfl_xor_sync(0xffffffffu, s10, o);
            s11 += __shfl_xor_sync(0xffffffffu, s11, o);
            s12 += __shfl_xor_sync(0xffffffffu, s12, o);
        }
        if ((lane & 3) == 0) {
            const int rl = wm * 64 + mi * 16 + (lane >> 2);
            atomicAdd(&sred[rl * NC + 0], s00);
            atomicAdd(&sred[rl * NC + 1], s01);
            atomicAdd(&sred[rl * NC + 2], s02);
            atomicAdd(&sred[(rl + 8) * NC + 0], s10);
            atomicAdd(&sred[(rl + 8) * NC + 1], s11);
            atomicAdd(&sred[(rl + 8) * NC + 2], s12);
        }
    }
    __syncthreads();

    if (t < BM) {
        const int row = row0 + t;
        const float gw = g_gate[row * NE + e];
        atomicAdd(&out[row * NC + 0], gw * sred[t * NC + 0]);
        atomicAdd(&out[row * NC + 1], gw * sred[t * NC + 1]);
        atomicAdd(&out[row * NC + 2], gw * sred[t * NC + 2]);
    }
}

// ==================================================================================
extern "C" void kernel_launch(void* const* d_in, const int* in_sizes, int n_in,
                              void* d_out, int out_size)
{
    const float* x       = (const float*)d_in[0];
    const float* gln_g   = (const float*)d_in[1];
    const float* gln_b   = (const float*)d_in[2];
    const float* gate_w  = (const float*)d_in[3];
    const float* gate_b  = (const float*)d_in[4];
    const float* ex_ln_g = (const float*)d_in[5];
    const float* ex_ln_b = (const float*)d_in[6];
    const float* ex_w1   = (const float*)d_in[7];
    const float* ex_b1   = (const float*)d_in[8];
    const float* ex_w2   = (const float*)d_in[9];
    const float* ex_b2   = (const float*)d_in[10];
    float* out = (float*)d_out;

    cudaFuncSetAttribute(gemm_kernel, cudaFuncAttributeMaxDynamicSharedMemorySize, DYN_SMEM);

    ln_gate_kernel<<<B_TOK, 256>>>(x, gln_g, gln_b, gate_w, gate_b, ex_b2, out);
    fold_w1_kernel<<<dim3(HID / 32, DIM / 32, NE), dim3(32, 8)>>>(ex_w1, ex_ln_g);
    fold_b1_kernel<<<dim3(HID / 256, NE), 256>>>(ex_w1, ex_ln_b, ex_b1);
    gemm_kernel<<<dim3(B_TOK / BM, NTOT / BN), 256, DYN_SMEM>>>(ex_w2, out);
}